// round 11
// baseline (speedup 1.0000x reference)
#include <cuda_runtime.h>
#include <cstdint>
#include <cstddef>

#define BDIM 8192
#define CDIM 256
#define NITER 100
#define NBLKMAX 1024
#define L2E 1.4426950408889634f
#define LN2 0.69314718055994531f

// Scratch: __device__ globals (no cudaMalloc allowed)
__device__ __align__(256) float g_M [(size_t)BDIM * BDIM];      // M[i][j] = 2*x_i.y_j
__device__ __align__(256) float g_b[BDIM];
__device__ __align__(256) float g_colm[(size_t)NBLKMAX * BDIM]; // per-block col max partial
__device__ __align__(256) float g_cols[(size_t)NBLKMAX * BDIM]; // per-block col sum partial

__device__ __forceinline__ float ex2f(float x) {
    float y; asm("ex2.approx.f32 %0, %1;" : "=f"(y) : "f"(x)); return y;
}
__device__ __forceinline__ float lg2f(float x) {
    float y; asm("lg2.approx.f32 %0, %1;" : "=f"(y) : "f"(x)); return y;
}

// ---------------------------------------------------------------------------
// b init: b[j] = -||y_j||^2   (one warp per row, 8 rows per block)
// ---------------------------------------------------------------------------
__global__ __launch_bounds__(256) void init_b_kernel(const float* __restrict__ Y)
{
    int warp = threadIdx.x >> 5, lane = threadIdx.x & 31;
    int row = (blockIdx.x << 3) + warp;
    const float4* yr = (const float4*)Y + (size_t)row * (CDIM / 4);
    float4 v0 = yr[lane];
    float4 v1 = yr[lane + 32];
    float ss = 0.f;
    ss = fmaf(v0.x, v0.x, ss); ss = fmaf(v0.y, v0.y, ss);
    ss = fmaf(v0.z, v0.z, ss); ss = fmaf(v0.w, v0.w, ss);
    ss = fmaf(v1.x, v1.x, ss); ss = fmaf(v1.y, v1.y, ss);
    ss = fmaf(v1.z, v1.z, ss); ss = fmaf(v1.w, v1.w, ss);
    #pragma unroll
    for (int off = 16; off; off >>= 1)
        ss += __shfl_xor_sync(0xffffffffu, ss, off);
    if (lane == 0) g_b[row] = -ss;
}

// ---------------------------------------------------------------------------
// GEMM: M = 2 * X * Y^T (row-major only; MT no longer needed).
// 128x128 tile, 256 threads, 8x8 per thread, k-step 16. (R6 proven version)
// ---------------------------------------------------------------------------
__global__ __launch_bounds__(256) void gemm_kernel(const float* __restrict__ X,
                                                   const float* __restrict__ Y)
{
    __shared__ float As[16][128];
    __shared__ float Bs[16][128];

    const int tid = threadIdx.x;
    const int tx = tid & 15;
    const int ty = tid >> 4;
    const int i0 = blockIdx.y << 7;
    const int j0 = blockIdx.x << 7;

    const float4* X4 = (const float4*)X;
    const float4* Y4 = (const float4*)Y;

    float acc[8][8];
    #pragma unroll
    for (int r = 0; r < 8; r++)
        #pragma unroll
        for (int c = 0; c < 8; c++) acc[r][c] = 0.f;

    for (int k0 = 0; k0 < CDIM; k0 += 16) {
        #pragma unroll
        for (int p = 0; p < 2; p++) {
            int f = tid + (p << 8);
            int r = f >> 2;
            int q = f & 3;
            float4 a = X4[(size_t)(i0 + r) * (CDIM / 4) + (k0 >> 2) + q];
            As[q * 4 + 0][r] = a.x; As[q * 4 + 1][r] = a.y;
            As[q * 4 + 2][r] = a.z; As[q * 4 + 3][r] = a.w;
            float4 b = Y4[(size_t)(j0 + r) * (CDIM / 4) + (k0 >> 2) + q];
            Bs[q * 4 + 0][r] = b.x; Bs[q * 4 + 1][r] = b.y;
            Bs[q * 4 + 2][r] = b.z; Bs[q * 4 + 3][r] = b.w;
        }
        __syncthreads();
        #pragma unroll
        for (int kk = 0; kk < 16; kk++) {
            float af[8], bf[8];
            *(float4*)&af[0] = *(const float4*)&As[kk][ty * 8];
            *(float4*)&af[4] = *(const float4*)&As[kk][ty * 8 + 4];
            *(float4*)&bf[0] = *(const float4*)&Bs[kk][tx * 8];
            *(float4*)&bf[4] = *(const float4*)&Bs[kk][tx * 8 + 4];
            #pragma unroll
            for (int r = 0; r < 8; r++)
                #pragma unroll
                for (int c = 0; c < 8; c++)
                    acc[r][c] = fmaf(af[r], bf[c], acc[r][c]);
        }
        __syncthreads();
    }

    #pragma unroll
    for (int r = 0; r < 8; r++) {
        int i = i0 + ty * 8 + r;
        float4 w0 = make_float4(2.f * acc[r][0], 2.f * acc[r][1],
                                2.f * acc[r][2], 2.f * acc[r][3]);
        float4 w1 = make_float4(2.f * acc[r][4], 2.f * acc[r][5],
                                2.f * acc[r][6], 2.f * acc[r][7]);
        float4* dst = (float4*)(g_M + (size_t)i * BDIM + j0 + tx * 8);
        dst[0] = w0; dst[1] = w1;
    }
}

// ---------------------------------------------------------------------------
// Fused Sinkhorn iteration (one sweep of M per iteration):
//   For each owned row i: a_i = -lse_j(M_ij + b_j)           (row phase)
//   Col partials: online (max,sum) over c_ij = (M_ij+b_j)+a_i (from registers)
//   b_new_j = b_old_j - lse_i(c_ij)  -- finished by reduce_b_kernel.
// c <= 0 always (max_j c_ij = -log s_i <= 0), so exp never overflows.
// One block = 512 threads = 16 warps; warp w owns column stripe [512w,512w+512).
// Rows processed in pairs; per-row-pair: 2 barriers (partial write + a ready).
// Col state (cm,cs) is warp-stripe-private -> no races, no fences.
// ---------------------------------------------------------------------------
__global__ __launch_bounds__(512, 2) void fused_iter_kernel(const float* __restrict__ Mmat,
                                                            const float* __restrict__ bsrc,
                                                            float* __restrict__ colm,
                                                            float* __restrict__ cols)
{
    extern __shared__ float dsm[];
    float* sb  = dsm;              // 8192: staged b
    float* cm  = dsm + 8192;       // 8192: per-col running max
    float* cs  = dsm + 16384;      // 8192: per-col running sum
    float* pm0 = dsm + 24576;      // 16 stripe maxes, row 0
    float* ps0 = pm0 + 16;         // 16 stripe sums,  row 0
    float* pm1 = ps0 + 16;         // 16 stripe maxes, row 1
    float* ps1 = pm1 + 16;         // 16 stripe sums,  row 1
    float* sa  = ps1 + 16;         // 2: a0, a1

    const int tid = threadIdx.x;
    const int lane = tid & 31, warp = tid >> 5;
    const int nblk = gridDim.x;
    const int r0 = (int)(((long long)BDIM * blockIdx.x) / nblk);
    const int r1 = (int)(((long long)BDIM * (blockIdx.x + 1)) / nblk);

    // stage b
    float4* sb4 = (float4*)sb;
    const float4* s4 = (const float4*)bsrc;
    #pragma unroll
    for (int k = 0; k < 4; k++) sb4[tid + 512 * k] = s4[tid + 512 * k];

    // init own stripe's col state (no barrier needed: stripe-private)
    float4* cm4 = (float4*)cm;
    float4* cs4 = (float4*)cs;
    const int sbase = warp * 128 + lane;     // float4 index of stripe element
    #pragma unroll
    for (int u = 0; u < 4; u++) {
        cm4[sbase + 32 * u] = make_float4(-3.0e38f, -3.0e38f, -3.0e38f, -3.0e38f);
        cs4[sbase + 32 * u] = make_float4(0.f, 0.f, 0.f, 0.f);
    }
    __syncthreads();

    for (int r = r0; r < r1; r += 2) {
        const bool dual = (r + 1 < r1);
        const float4* row0 = (const float4*)Mmat + ((size_t)r << 11);
        float4 v0[4], v1[4];
        #pragma unroll
        for (int u = 0; u < 4; u++) {
            float4 mm = __ldcs(row0 + sbase + 32 * u);
            float4 bb = sb4[sbase + 32 * u];
            v0[u].x = mm.x + bb.x; v0[u].y = mm.y + bb.y;
            v0[u].z = mm.z + bb.z; v0[u].w = mm.w + bb.w;
        }
        if (dual) {
            const float4* row1 = row0 + 2048;
            #pragma unroll
            for (int u = 0; u < 4; u++) {
                float4 mm = __ldcs(row1 + sbase + 32 * u);
                float4 bb = sb4[sbase + 32 * u];
                v1[u].x = mm.x + bb.x; v1[u].y = mm.y + bb.y;
                v1[u].z = mm.z + bb.z; v1[u].w = mm.w + bb.w;
            }
        }

        // stripe-local (max,sum) for row 0
        {
            float m = -3.0e38f;
            #pragma unroll
            for (int u = 0; u < 4; u++)
                m = fmaxf(m, fmaxf(fmaxf(v0[u].x, v0[u].y), fmaxf(v0[u].z, v0[u].w)));
            #pragma unroll
            for (int off = 16; off; off >>= 1)
                m = fmaxf(m, __shfl_xor_sync(0xffffffffu, m, off));
            float mk = m * L2E, s = 0.f;
            #pragma unroll
            for (int u = 0; u < 4; u++) {
                s += ex2f(fmaf(v0[u].x, L2E, -mk));
                s += ex2f(fmaf(v0[u].y, L2E, -mk));
                s += ex2f(fmaf(v0[u].z, L2E, -mk));
                s += ex2f(fmaf(v0[u].w, L2E, -mk));
            }
            #pragma unroll
            for (int off = 16; off; off >>= 1)
                s += __shfl_xor_sync(0xffffffffu, s, off);
            if (lane == 0) { pm0[warp] = m; ps0[warp] = s; }
        }
        if (dual) {
            float m = -3.0e38f;
            #pragma unroll
            for (int u = 0; u < 4; u++)
                m = fmaxf(m, fmaxf(fmaxf(v1[u].x, v1[u].y), fmaxf(v1[u].z, v1[u].w)));
            #pragma unroll
            for (int off = 16; off; off >>= 1)
                m = fmaxf(m, __shfl_xor_sync(0xffffffffu, m, off));
            float mk = m * L2E, s = 0.f;
            #pragma unroll
            for (int u = 0; u < 4; u++) {
                s += ex2f(fmaf(v1[u].x, L2E, -mk));
                s += ex2f(fmaf(v1[u].y, L2E, -mk));
                s += ex2f(fmaf(v1[u].z, L2E, -mk));
                s += ex2f(fmaf(v1[u].w, L2E, -mk));
            }
            #pragma unroll
            for (int off = 16; off; off >>= 1)
                s += __shfl_xor_sync(0xffffffffu, s, off);
            if (lane == 0) { pm1[warp] = m; ps1[warp] = s; }
        }
        __syncthreads();

        // warp 0 combines 16 stripe pairs per row (lanes 0-15: row0, 16-31: row1)
        if (warp == 0) {
            int stripe = lane & 15, rsel = lane >> 4;
            float m = rsel ? pm1[stripe] : pm0[stripe];
            float s = rsel ? ps1[stripe] : ps0[stripe];
            float mm = m;
            #pragma unroll
            for (int off = 1; off <= 8; off <<= 1)
                mm = fmaxf(mm, __shfl_xor_sync(0xffffffffu, mm, off));
            float t = s * ex2f((m - mm) * L2E);
            #pragma unroll
            for (int off = 1; off <= 8; off <<= 1)
                t += __shfl_xor_sync(0xffffffffu, t, off);
            if ((lane & 15) == 0) sa[rsel] = -(mm + lg2f(t) * LN2);
        }
        __syncthreads();
        const float a0 = sa[0];
        const float a1 = dual ? sa[1] : 0.f;

        // col update from registers (stripe-private smem state)
        #pragma unroll
        for (int u = 0; u < 4; u++) {
            float4 cmv = cm4[sbase + 32 * u];
            float4 csv = cs4[sbase + 32 * u];
            #define COLUPD(C)                                                     \
            {                                                                     \
                float c0 = v0[u].C + a0;                                          \
                float c1 = dual ? (v1[u].C + a1) : -3.0e38f;                      \
                float cc = fmaxf(c0, c1);                                         \
                if (cc <= cmv.C) {                                                \
                    float add = ex2f((c0 - cmv.C) * L2E);                         \
                    if (dual) add += ex2f((c1 - cmv.C) * L2E);                    \
                    csv.C += add;                                                 \
                } else {                                                          \
                    float ns = csv.C * ex2f((cmv.C - cc) * L2E)                   \
                             + ex2f((c0 - cc) * L2E);                             \
                    if (dual) ns += ex2f((c1 - cc) * L2E);                        \
                    cmv.C = cc; csv.C = ns;                                       \
                }                                                                 \
            }
            COLUPD(x) COLUPD(y) COLUPD(z) COLUPD(w)
            #undef COLUPD
            cm4[sbase + 32 * u] = cmv;
            cs4[sbase + 32 * u] = csv;
        }
    }
    __syncthreads();

    // write block partials (coalesced)
    float* cmo = colm + (size_t)blockIdx.x * BDIM;
    float* cso = cols + (size_t)blockIdx.x * BDIM;
    #pragma unroll
    for (int k = 0; k < 16; k++) {
        int j = tid + 512 * k;
        cmo[j] = cm[j];
        cso[j] = cs[j];
    }
}

// ---------------------------------------------------------------------------
// Combine block col partials in fixed block order: b[j] -= lse_i(c_ij)
// ---------------------------------------------------------------------------
__global__ __launch_bounds__(256) void reduce_b_kernel(const float* __restrict__ colm,
                                                       const float* __restrict__ cols,
                                                       float* __restrict__ b, int nblk)
{
    int j = blockIdx.x * 256 + threadIdx.x;
    float m = -3.0e38f, s = 0.f;
    for (int k = 0; k < nblk; k++) {
        float bm = colm[(size_t)k * BDIM + j];
        float bs = cols[(size_t)k * BDIM + j];
        if (bm <= m) {
            s += bs * ex2f((bm - m) * L2E);
        } else {
            s = s * ex2f((m - bm) * L2E) + bs;
            m = bm;
        }
    }
    b[j] = b[j] - (m + lg2f(s) * LN2);
}

// ---------------------------------------------------------------------------
// Final: out[i][:] = y[ argmax_j (M[i][j] + b[j]) ][:]
// ---------------------------------------------------------------------------
__global__ __launch_bounds__(256) void argmax_gather_kernel(const float* __restrict__ Y,
                                                            float* __restrict__ out)
{
    __shared__ float sb[BDIM];
    __shared__ float sval[8];
    __shared__ int   sidx[8];
    __shared__ int   sjbest;
    const int tid = threadIdx.x;
    const int lane = tid & 31, warp = tid >> 5;

    float4* sb4 = (float4*)sb;
    const float4* s4 = (const float4*)g_b;
    #pragma unroll
    for (int k = 0; k < 8; k++) sb4[tid + 256 * k] = s4[tid + 256 * k];
    __syncthreads();

    const int row0 = blockIdx.x << 3;
    for (int rr = 0; rr < 8; rr++) {
        const int row = row0 + rr;
        const float4* m4 = (const float4*)(g_M + (size_t)row * BDIM);

        float best = -3.0e38f;
        int bidx = 0x7fffffff;
        #pragma unroll
        for (int k = 0; k < 8; k++) {
            int f = tid + 256 * k;
            float4 m = __ldcs(m4 + f);
            float4 bb = sb4[f];
            float vx = m.x + bb.x, vy = m.y + bb.y, vz = m.z + bb.z, vw = m.w + bb.w;
            int j = f * 4;
            if (vx > best || (vx == best && j     < bidx)) { best = vx; bidx = j; }
            if (vy > best || (vy == best && j + 1 < bidx)) { best = vy; bidx = j + 1; }
            if (vz > best || (vz == best && j + 2 < bidx)) { best = vz; bidx = j + 2; }
            if (vw > best || (vw == best && j + 3 < bidx)) { best = vw; bidx = j + 3; }
        }
        #pragma unroll
        for (int off = 16; off; off >>= 1) {
            float ov = __shfl_xor_sync(0xffffffffu, best, off);
            int   oi = __shfl_xor_sync(0xffffffffu, bidx, off);
            if (ov > best || (ov == best && oi < bidx)) { best = ov; bidx = oi; }
        }
        if (lane == 0) { sval[warp] = best; sidx[warp] = bidx; }
        __syncthreads();
        if (tid == 0) {
            float bv = sval[0]; int bj = sidx[0];
            #pragma unroll
            for (int w = 1; w < 8; w++) {
                if (sval[w] > bv || (sval[w] == bv && sidx[w] < bj)) {
                    bv = sval[w]; bj = sidx[w];
                }
            }
            sjbest = bj;
        }
        __syncthreads();
        out[(size_t)row * CDIM + tid] = Y[(size_t)sjbest * CDIM + tid];
        __syncthreads();
    }
}

// ---------------------------------------------------------------------------
extern "C" void kernel_launch(void* const* d_in, const int* in_sizes, int n_in,
                              void* d_out, int out_size)
{
    const float* X = (const float*)d_in[0];
    const float* Y = (const float*)d_in[1];
    float* out = (float*)d_out;

    float *Mp, *bp, *cmp, *csp;
    cudaGetSymbolAddress((void**)&Mp,  g_M);
    cudaGetSymbolAddress((void**)&bp,  g_b);
    cudaGetSymbolAddress((void**)&cmp, g_colm);
    cudaGetSymbolAddress((void**)&csp, g_cols);

    int nsm = 148;
    cudaDeviceGetAttribute(&nsm, cudaDevAttrMultiProcessorCount, 0);
    int grid = 2 * nsm;
    if (grid > NBLKMAX) grid = NBLKMAX;

    const int smem_bytes = (3 * BDIM + 66) * (int)sizeof(float);
    cudaFuncSetAttribute(fused_iter_kernel,
                         cudaFuncAttributeMaxDynamicSharedMemorySize, smem_bytes);

    init_b_kernel<<<BDIM / 8, 256>>>(Y);

    dim3 ggrid(BDIM / 128, BDIM / 128);
    gemm_kernel<<<ggrid, 256>>>(X, Y);

    for (int it = 0; it < NITER; it++) {
        fused_iter_kernel<<<grid, 512, smem_bytes>>>(Mp, bp, cmp, csp);
        reduce_b_kernel<<<BDIM / 256, 256>>>(cmp, csp, bp, grid);
    }

    argmax_gather_kernel<<<BDIM / 8, 256>>>(Y, out);
}

// round 12
// speedup vs baseline: 1.1525x; 1.1525x over previous
#include <cuda_runtime.h>
#include <cstdint>
#include <cstddef>

#define BDIM 8192
#define CDIM 256
#define NITER 100
#define NBLKMAX 1024
#define NSEG 8
#define L2E 1.4426950408889634f
#define LN2 0.69314718055994531f

// Scratch: __device__ globals (no cudaMalloc allowed)
__device__ __align__(256) float g_M [(size_t)BDIM * BDIM];      // M[i][j] = 2*x_i.y_j
__device__ __align__(256) float g_b[BDIM];
__device__ __align__(256) float g_colm[(size_t)NBLKMAX * BDIM]; // per-block col max partial
__device__ __align__(256) float g_cols[(size_t)NBLKMAX * BDIM]; // per-block col sum partial

__device__ __forceinline__ float ex2f(float x) {
    float y; asm("ex2.approx.f32 %0, %1;" : "=f"(y) : "f"(x)); return y;
}
__device__ __forceinline__ float lg2f(float x) {
    float y; asm("lg2.approx.f32 %0, %1;" : "=f"(y) : "f"(x)); return y;
}

// ---------------------------------------------------------------------------
// b init: b[j] = -||y_j||^2   (one warp per row, 8 rows per block)
// ---------------------------------------------------------------------------
__global__ __launch_bounds__(256) void init_b_kernel(const float* __restrict__ Y)
{
    int warp = threadIdx.x >> 5, lane = threadIdx.x & 31;
    int row = (blockIdx.x << 3) + warp;
    const float4* yr = (const float4*)Y + (size_t)row * (CDIM / 4);
    float4 v0 = yr[lane];
    float4 v1 = yr[lane + 32];
    float ss = 0.f;
    ss = fmaf(v0.x, v0.x, ss); ss = fmaf(v0.y, v0.y, ss);
    ss = fmaf(v0.z, v0.z, ss); ss = fmaf(v0.w, v0.w, ss);
    ss = fmaf(v1.x, v1.x, ss); ss = fmaf(v1.y, v1.y, ss);
    ss = fmaf(v1.z, v1.z, ss); ss = fmaf(v1.w, v1.w, ss);
    #pragma unroll
    for (int off = 16; off; off >>= 1)
        ss += __shfl_xor_sync(0xffffffffu, ss, off);
    if (lane == 0) g_b[row] = -ss;
}

// ---------------------------------------------------------------------------
// GEMM: M = 2 * X * Y^T (row-major only; MT not needed).
// ---------------------------------------------------------------------------
__global__ __launch_bounds__(256) void gemm_kernel(const float* __restrict__ X,
                                                   const float* __restrict__ Y)
{
    __shared__ float As[16][128];
    __shared__ float Bs[16][128];

    const int tid = threadIdx.x;
    const int tx = tid & 15;
    const int ty = tid >> 4;
    const int i0 = blockIdx.y << 7;
    const int j0 = blockIdx.x << 7;

    const float4* X4 = (const float4*)X;
    const float4* Y4 = (const float4*)Y;

    float acc[8][8];
    #pragma unroll
    for (int r = 0; r < 8; r++)
        #pragma unroll
        for (int c = 0; c < 8; c++) acc[r][c] = 0.f;

    for (int k0 = 0; k0 < CDIM; k0 += 16) {
        #pragma unroll
        for (int p = 0; p < 2; p++) {
            int f = tid + (p << 8);
            int r = f >> 2;
            int q = f & 3;
            float4 a = X4[(size_t)(i0 + r) * (CDIM / 4) + (k0 >> 2) + q];
            As[q * 4 + 0][r] = a.x; As[q * 4 + 1][r] = a.y;
            As[q * 4 + 2][r] = a.z; As[q * 4 + 3][r] = a.w;
            float4 b = Y4[(size_t)(j0 + r) * (CDIM / 4) + (k0 >> 2) + q];
            Bs[q * 4 + 0][r] = b.x; Bs[q * 4 + 1][r] = b.y;
            Bs[q * 4 + 2][r] = b.z; Bs[q * 4 + 3][r] = b.w;
        }
        __syncthreads();
        #pragma unroll
        for (int kk = 0; kk < 16; kk++) {
            float af[8], bf[8];
            *(float4*)&af[0] = *(const float4*)&As[kk][ty * 8];
            *(float4*)&af[4] = *(const float4*)&As[kk][ty * 8 + 4];
            *(float4*)&bf[0] = *(const float4*)&Bs[kk][tx * 8];
            *(float4*)&bf[4] = *(const float4*)&Bs[kk][tx * 8 + 4];
            #pragma unroll
            for (int r = 0; r < 8; r++)
                #pragma unroll
                for (int c = 0; c < 8; c++)
                    acc[r][c] = fmaf(af[r], bf[c], acc[r][c]);
        }
        __syncthreads();
    }

    #pragma unroll
    for (int r = 0; r < 8; r++) {
        int i = i0 + ty * 8 + r;
        float4 w0 = make_float4(2.f * acc[r][0], 2.f * acc[r][1],
                                2.f * acc[r][2], 2.f * acc[r][3]);
        float4 w1 = make_float4(2.f * acc[r][4], 2.f * acc[r][5],
                                2.f * acc[r][6], 2.f * acc[r][7]);
        float4* dst = (float4*)(g_M + (size_t)i * BDIM + j0 + tx * 8);
        dst[0] = w0; dst[1] = w1;
    }
}

// ---------------------------------------------------------------------------
// Fused Sinkhorn iteration (one sweep of M per iteration):
//   a_i = -lse_j(M_ij + b_j); col partials over c_ij = (M_ij+b_j)+a_i <= 0.
//   b_new_j = b_old_j - lse_i(c_ij)  -- finished by reduce_b_kernel.
// One block = 512 threads = 16 warps; warp w owns column stripe [512w,512w+512).
// ---------------------------------------------------------------------------
__global__ __launch_bounds__(512, 2) void fused_iter_kernel(const float* __restrict__ Mmat,
                                                            const float* __restrict__ bsrc,
                                                            float* __restrict__ colm,
                                                            float* __restrict__ cols)
{
    extern __shared__ float dsm[];
    float* sb  = dsm;              // 8192: staged b
    float* cm  = dsm + 8192;       // 8192: per-col running max
    float* cs  = dsm + 16384;      // 8192: per-col running sum
    float* pm0 = dsm + 24576;      // 16 stripe maxes, row 0
    float* ps0 = pm0 + 16;         // 16 stripe sums,  row 0
    float* pm1 = ps0 + 16;         // 16 stripe maxes, row 1
    float* ps1 = pm1 + 16;         // 16 stripe sums,  row 1
    float* sa  = ps1 + 16;         // 2: a0, a1

    const int tid = threadIdx.x;
    const int lane = tid & 31, warp = tid >> 5;
    const int nblk = gridDim.x;
    const int r0 = (int)(((long long)BDIM * blockIdx.x) / nblk);
    const int r1 = (int)(((long long)BDIM * (blockIdx.x + 1)) / nblk);

    // stage b
    float4* sb4 = (float4*)sb;
    const float4* s4 = (const float4*)bsrc;
    #pragma unroll
    for (int k = 0; k < 4; k++) sb4[tid + 512 * k] = s4[tid + 512 * k];

    // init own stripe's col state (stripe-private)
    float4* cm4 = (float4*)cm;
    float4* cs4 = (float4*)cs;
    const int sbase = warp * 128 + lane;
    #pragma unroll
    for (int u = 0; u < 4; u++) {
        cm4[sbase + 32 * u] = make_float4(-3.0e38f, -3.0e38f, -3.0e38f, -3.0e38f);
        cs4[sbase + 32 * u] = make_float4(0.f, 0.f, 0.f, 0.f);
    }
    __syncthreads();

    for (int r = r0; r < r1; r += 2) {
        const bool dual = (r + 1 < r1);
        const float4* row0 = (const float4*)Mmat + ((size_t)r << 11);
        float4 v0[4], v1[4];
        #pragma unroll
        for (int u = 0; u < 4; u++) {
            float4 mm = __ldcs(row0 + sbase + 32 * u);
            float4 bb = sb4[sbase + 32 * u];
            v0[u].x = mm.x + bb.x; v0[u].y = mm.y + bb.y;
            v0[u].z = mm.z + bb.z; v0[u].w = mm.w + bb.w;
        }
        if (dual) {
            const float4* row1 = row0 + 2048;
            #pragma unroll
            for (int u = 0; u < 4; u++) {
                float4 mm = __ldcs(row1 + sbase + 32 * u);
                float4 bb = sb4[sbase + 32 * u];
                v1[u].x = mm.x + bb.x; v1[u].y = mm.y + bb.y;
                v1[u].z = mm.z + bb.z; v1[u].w = mm.w + bb.w;
            }
        }

        {
            float m = -3.0e38f;
            #pragma unroll
            for (int u = 0; u < 4; u++)
                m = fmaxf(m, fmaxf(fmaxf(v0[u].x, v0[u].y), fmaxf(v0[u].z, v0[u].w)));
            #pragma unroll
            for (int off = 16; off; off >>= 1)
                m = fmaxf(m, __shfl_xor_sync(0xffffffffu, m, off));
            float mk = m * L2E, s = 0.f;
            #pragma unroll
            for (int u = 0; u < 4; u++) {
                s += ex2f(fmaf(v0[u].x, L2E, -mk));
                s += ex2f(fmaf(v0[u].y, L2E, -mk));
                s += ex2f(fmaf(v0[u].z, L2E, -mk));
                s += ex2f(fmaf(v0[u].w, L2E, -mk));
            }
            #pragma unroll
            for (int off = 16; off; off >>= 1)
                s += __shfl_xor_sync(0xffffffffu, s, off);
            if (lane == 0) { pm0[warp] = m; ps0[warp] = s; }
        }
        if (dual) {
            float m = -3.0e38f;
            #pragma unroll
            for (int u = 0; u < 4; u++)
                m = fmaxf(m, fmaxf(fmaxf(v1[u].x, v1[u].y), fmaxf(v1[u].z, v1[u].w)));
            #pragma unroll
            for (int off = 16; off; off >>= 1)
                m = fmaxf(m, __shfl_xor_sync(0xffffffffu, m, off));
            float mk = m * L2E, s = 0.f;
            #pragma unroll
            for (int u = 0; u < 4; u++) {
                s += ex2f(fmaf(v1[u].x, L2E, -mk));
                s += ex2f(fmaf(v1[u].y, L2E, -mk));
                s += ex2f(fmaf(v1[u].z, L2E, -mk));
                s += ex2f(fmaf(v1[u].w, L2E, -mk));
            }
            #pragma unroll
            for (int off = 16; off; off >>= 1)
                s += __shfl_xor_sync(0xffffffffu, s, off);
            if (lane == 0) { pm1[warp] = m; ps1[warp] = s; }
        }
        __syncthreads();

        if (warp == 0) {
            int stripe = lane & 15, rsel = lane >> 4;
            float m = rsel ? pm1[stripe] : pm0[stripe];
            float s = rsel ? ps1[stripe] : ps0[stripe];
            float mm = m;
            #pragma unroll
            for (int off = 1; off <= 8; off <<= 1)
                mm = fmaxf(mm, __shfl_xor_sync(0xffffffffu, mm, off));
            float t = s * ex2f((m - mm) * L2E);
            #pragma unroll
            for (int off = 1; off <= 8; off <<= 1)
                t += __shfl_xor_sync(0xffffffffu, t, off);
            if ((lane & 15) == 0) sa[rsel] = -(mm + lg2f(t) * LN2);
        }
        __syncthreads();
        const float a0 = sa[0];
        const float a1 = dual ? sa[1] : 0.f;

        #pragma unroll
        for (int u = 0; u < 4; u++) {
            float4 cmv = cm4[sbase + 32 * u];
            float4 csv = cs4[sbase + 32 * u];
            #define COLUPD(C)                                                     \
            {                                                                     \
                float c0 = v0[u].C + a0;                                          \
                float c1 = dual ? (v1[u].C + a1) : -3.0e38f;                      \
                float cc = fmaxf(c0, c1);                                         \
                if (cc <= cmv.C) {                                                \
                    float add = ex2f((c0 - cmv.C) * L2E);                         \
                    if (dual) add += ex2f((c1 - cmv.C) * L2E);                    \
                    csv.C += add;                                                 \
                } else {                                                          \
                    float ns = csv.C * ex2f((cmv.C - cc) * L2E)                   \
                             + ex2f((c0 - cc) * L2E);                             \
                    if (dual) ns += ex2f((c1 - cc) * L2E);                        \
                    cmv.C = cc; csv.C = ns;                                       \
                }                                                                 \
            }
            COLUPD(x) COLUPD(y) COLUPD(z) COLUPD(w)
            #undef COLUPD
            cm4[sbase + 32 * u] = cmv;
            cs4[sbase + 32 * u] = csv;
        }
    }
    __syncthreads();

    float* cmo = colm + (size_t)blockIdx.x * BDIM;
    float* cso = cols + (size_t)blockIdx.x * BDIM;
    #pragma unroll
    for (int k = 0; k < 16; k++) {
        int j = tid + 512 * k;
        cmo[j] = cm[j];
        cso[j] = cs[j];
    }
}

// ---------------------------------------------------------------------------
// Hierarchical combine: 8 threads per column (8 k-segments), fixed order.
// Grid 256 x 256 threads: lane -> column within 32-col group, warp -> segment.
// ---------------------------------------------------------------------------
__global__ __launch_bounds__(256) void reduce_b_kernel(const float* __restrict__ colm,
                                                       const float* __restrict__ cols,
                                                       float* __restrict__ b, int nblk)
{
    __shared__ float sm_m[NSEG][32];
    __shared__ float sm_s[NSEG][32];
    const int lane32 = threadIdx.x & 31;
    const int seg = threadIdx.x >> 5;
    const int j = blockIdx.x * 32 + lane32;
    const int k0 = seg * nblk / NSEG;
    const int k1 = (seg + 1) * nblk / NSEG;

    float m = -3.0e38f, s = 0.f;
    for (int k = k0; k < k1; k++) {
        float bm = colm[(size_t)k * BDIM + j];
        float bs = cols[(size_t)k * BDIM + j];
        if (bm <= m) {
            s += bs * ex2f((bm - m) * L2E);
        } else {
            s = s * ex2f((m - bm) * L2E) + bs;
            m = bm;
        }
    }
    sm_m[seg][lane32] = m;
    sm_s[seg][lane32] = s;
    __syncthreads();

    if (threadIdx.x < 32) {
        float mm = sm_m[0][lane32], ss = sm_s[0][lane32];
        #pragma unroll
        for (int k = 1; k < NSEG; k++) {
            float bm = sm_m[k][lane32], bs = sm_s[k][lane32];
            if (bm <= mm) {
                ss += bs * ex2f((bm - mm) * L2E);
            } else {
                ss = ss * ex2f((mm - bm) * L2E) + bs;
                mm = bm;
            }
        }
        b[j] = b[j] - (mm + lg2f(ss) * LN2);
    }
}

// ---------------------------------------------------------------------------
// Final: out[i][:] = y[ argmax_j (M[i][j] + b[j]) ][:]
// ---------------------------------------------------------------------------
__global__ __launch_bounds__(256) void argmax_gather_kernel(const float* __restrict__ Y,
                                                            float* __restrict__ out)
{
    __shared__ float sb[BDIM];
    __shared__ float sval[8];
    __shared__ int   sidx[8];
    __shared__ int   sjbest;
    const int tid = threadIdx.x;
    const int lane = tid & 31, warp = tid >> 5;

    float4* sb4 = (float4*)sb;
    const float4* s4 = (const float4*)g_b;
    #pragma unroll
    for (int k = 0; k < 8; k++) sb4[tid + 256 * k] = s4[tid + 256 * k];
    __syncthreads();

    const int row0 = blockIdx.x << 3;
    for (int rr = 0; rr < 8; rr++) {
        const int row = row0 + rr;
        const float4* m4 = (const float4*)(g_M + (size_t)row * BDIM);

        float best = -3.0e38f;
        int bidx = 0x7fffffff;
        #pragma unroll
        for (int k = 0; k < 8; k++) {
            int f = tid + 256 * k;
            float4 m = __ldcs(m4 + f);
            float4 bb = sb4[f];
            float vx = m.x + bb.x, vy = m.y + bb.y, vz = m.z + bb.z, vw = m.w + bb.w;
            int j = f * 4;
            if (vx > best || (vx == best && j     < bidx)) { best = vx; bidx = j; }
            if (vy > best || (vy == best && j + 1 < bidx)) { best = vy; bidx = j + 1; }
            if (vz > best || (vz == best && j + 2 < bidx)) { best = vz; bidx = j + 2; }
            if (vw > best || (vw == best && j + 3 < bidx)) { best = vw; bidx = j + 3; }
        }
        #pragma unroll
        for (int off = 16; off; off >>= 1) {
            float ov = __shfl_xor_sync(0xffffffffu, best, off);
            int   oi = __shfl_xor_sync(0xffffffffu, bidx, off);
            if (ov > best || (ov == best && oi < bidx)) { best = ov; bidx = oi; }
        }
        if (lane == 0) { sval[warp] = best; sidx[warp] = bidx; }
        __syncthreads();
        if (tid == 0) {
            float bv = sval[0]; int bj = sidx[0];
            #pragma unroll
            for (int w = 1; w < 8; w++) {
                if (sval[w] > bv || (sval[w] == bv && sidx[w] < bj)) {
                    bv = sval[w]; bj = sidx[w];
                }
            }
            sjbest = bj;
        }
        __syncthreads();
        out[(size_t)row * CDIM + tid] = Y[(size_t)sjbest * CDIM + tid];
        __syncthreads();
    }
}

// ---------------------------------------------------------------------------
extern "C" void kernel_launch(void* const* d_in, const int* in_sizes, int n_in,
                              void* d_out, int out_size)
{
    const float* X = (const float*)d_in[0];
    const float* Y = (const float*)d_in[1];
    float* out = (float*)d_out;

    float *Mp, *bp, *cmp, *csp;
    cudaGetSymbolAddress((void**)&Mp,  g_M);
    cudaGetSymbolAddress((void**)&bp,  g_b);
    cudaGetSymbolAddress((void**)&cmp, g_colm);
    cudaGetSymbolAddress((void**)&csp, g_cols);

    int nsm = 148;
    cudaDeviceGetAttribute(&nsm, cudaDevAttrMultiProcessorCount, 0);
    int grid = 2 * nsm;
    if (grid > NBLKMAX) grid = NBLKMAX;

    const int smem_bytes = (3 * BDIM + 66) * (int)sizeof(float);
    cudaFuncSetAttribute(fused_iter_kernel,
                         cudaFuncAttributeMaxDynamicSharedMemorySize, smem_bytes);

    init_b_kernel<<<BDIM / 8, 256>>>(Y);

    dim3 ggrid(BDIM / 128, BDIM / 128);
    gemm_kernel<<<ggrid, 256>>>(X, Y);

    for (int it = 0; it < NITER; it++) {
        fused_iter_kernel<<<grid, 512, smem_bytes>>>(Mp, bp, cmp, csp);
        reduce_b_kernel<<<BDIM / 32, 256>>>(cmp, csp, bp, grid);
    }

    argmax_gather_kernel<<<BDIM / 8, 256>>>(Y, out);
}